// round 17
// baseline (speedup 1.0000x reference)
#include <cuda_runtime.h>
#include <cuda_bf16.h>
#include <math.h>
#include <stdint.h>

// Problem constants
#define NTOK   8192
#define EDIM   768
#define SEQ    256
#define NB     32
#define NH     12
#define HDIM   64
#define FFDIM  2048
#define E3     2304

// -------------------- scratch --------------------
__device__ float g_X  [NTOK * EDIM];
__device__ float g_Yb [NTOK * EDIM];
__device__ float g_O  [NTOK * EDIM];          // dense output
__device__ float g_AO [NTOK * EDIM];          // attention output (fp32)
__device__ float g_C  [NTOK];
__device__ float g_Ff [NTOK * FFDIM];

__device__ __nv_bfloat16 g_QKVh[NTOK * E3],  g_QKVl[NTOK * E3];

// int8 two-digit buffers
__device__ int8_t g_X1[NTOK * EDIM],  g_X0[NTOK * EDIM];
__device__ int8_t g_F1[NTOK * FFDIM], g_F0[NTOK * FFDIM];
__device__ int8_t g_Wq1[2 * E3 * EDIM],     g_Wq0[2 * E3 * EDIM];
__device__ int8_t g_Wo1[2 * EDIM * EDIM],   g_Wo0[2 * EDIM * EDIM];
__device__ int8_t g_W1d1[2 * FFDIM * EDIM], g_W1d0[2 * FFDIM * EDIM];
__device__ int8_t g_W2d1[2 * EDIM * FFDIM], g_W2d0[2 * EDIM * FFDIM];
__device__ int8_t g_Wdd1[EDIM * EDIM],      g_Wdd0[EDIM * EDIM];
__device__ float  g_sX[NTOK], g_sF[NTOK];
__device__ float  g_sWq[2 * E3], g_sWo[2 * EDIM];
__device__ float  g_sW1[2 * FFDIM], g_sW2[2 * EDIM], g_sWd[EDIM];

// -------------------- helpers --------------------
__device__ __forceinline__ uint32_t smem_u32(const void* p) {
    uint32_t a;
    asm("{ .reg .u64 t; cvta.to.shared.u64 t, %1; cvt.u32.u64 %0, t; }" : "=r"(a) : "l"(p));
    return a;
}
__device__ __forceinline__ void split_bf16(float v, __nv_bfloat16& h, __nv_bfloat16& l) {
    h = __float2bfloat16(v);
    l = __float2bfloat16(v - __bfloat162float(h));
}

#define CP_ASYNC16(saddr, gptr) \
    asm volatile("cp.async.cg.shared.global [%0], [%1], 16;" :: "r"(saddr), "l"(gptr))
#define CP_COMMIT() asm volatile("cp.async.commit_group;" ::: "memory")
#define CP_WAIT2()  asm volatile("cp.async.wait_group 2;" ::: "memory")
#define CP_WAIT0()  asm volatile("cp.async.wait_group 0;" ::: "memory")

#define LDSM4(r, addr) \
    asm volatile("ldmatrix.sync.aligned.m8n8.x4.shared.b16 {%0,%1,%2,%3}, [%4];" \
        : "=r"((r)[0]), "=r"((r)[1]), "=r"((r)[2]), "=r"((r)[3]) : "r"(addr))
#define LDSM4T(r, addr) \
    asm volatile("ldmatrix.sync.aligned.m8n8.x4.trans.shared.b16 {%0,%1,%2,%3}, [%4];" \
        : "=r"((r)[0]), "=r"((r)[1]), "=r"((r)[2]), "=r"((r)[3]) : "r"(addr))

#define MMA_BF16(c, a, b0, b1) \
    asm volatile("mma.sync.aligned.m16n8k16.row.col.f32.bf16.bf16.f32 " \
        "{%0,%1,%2,%3}, {%4,%5,%6,%7}, {%8,%9}, {%0,%1,%2,%3};" \
        : "+f"((c)[0]), "+f"((c)[1]), "+f"((c)[2]), "+f"((c)[3]) \
        : "r"((a)[0]), "r"((a)[1]), "r"((a)[2]), "r"((a)[3]), "r"(b0), "r"(b1))

#define MMA_S8(c, a, b0_, b1_) \
    asm volatile("mma.sync.aligned.m16n8k32.row.col.s32.s8.s8.s32 " \
        "{%0,%1,%2,%3}, {%4,%5,%6,%7}, {%8,%9}, {%0,%1,%2,%3};" \
        : "+r"((c)[0]), "+r"((c)[1]), "+r"((c)[2]), "+r"((c)[3]) \
        : "r"((a)[0]), "r"((a)[1]), "r"((a)[2]), "r"((a)[3]), "r"(b0_), "r"(b1_))

// -------------------- warp reductions --------------------
__device__ __forceinline__ float warp_sum(float v) {
    #pragma unroll
    for (int o = 16; o > 0; o >>= 1) v += __shfl_xor_sync(0xffffffffu, v, o);
    return v;
}
__device__ __forceinline__ float warp_max(float v) {
    #pragma unroll
    for (int o = 16; o > 0; o >>= 1) v = fmaxf(v, __shfl_xor_sync(0xffffffffu, v, o));
    return v;
}
__device__ __forceinline__ float block_sum256(float v, volatile float* red) {
    v = warp_sum(v);
    const int w = threadIdx.x >> 5;
    __syncthreads();
    if ((threadIdx.x & 31) == 0) red[w] = v;
    __syncthreads();
    return red[0] + red[1] + red[2] + red[3] + red[4] + red[5] + red[6] + red[7];
}

__device__ __forceinline__ void quant2(float q, int8_t& d1, int8_t& d0) {
    float a1 = rintf(q);
    float a0 = rintf((q - a1) * 254.0f);
    d1 = (int8_t)(int)a1;
    d0 = (int8_t)(int)a0;
}
__device__ __forceinline__ void quant4pack(float4 x, float rc, uint32_t& p1, uint32_t& p0) {
    union { int8_t b[4]; uint32_t u; } u1, u0;
    quant2(x.x * rc, u1.b[0], u0.b[0]);
    quant2(x.y * rc, u1.b[1], u0.b[1]);
    quant2(x.z * rc, u1.b[2], u0.b[2]);
    quant2(x.w * rc, u1.b[3], u0.b[3]);
    p1 = u1.u; p0 = u0.u;
}

// -------------------- per-row int8 quantizer (weights) --------------------
__global__ void __launch_bounds__(256) quant_rows_kernel(
    const float* __restrict__ src, int8_t* __restrict__ d1, int8_t* __restrict__ d0,
    float* __restrict__ sc, int K)
{
    const int row  = blockIdx.x * 8 + (threadIdx.x >> 5);
    const int lane = threadIdx.x & 31;
    const float* r = src + (size_t)row * K;
    const int NJ = K >> 7;
    float m = 0.f;
    for (int j = 0; j < NJ; j++) {
        float4 x = *(const float4*)(r + j * 128 + lane * 4);
        m = fmaxf(m, fmaxf(fmaxf(fabsf(x.x), fabsf(x.y)), fmaxf(fabsf(x.z), fabsf(x.w))));
    }
    m = warp_max(m);
    const float s = fmaxf(m, 1e-30f);
    const float rc = 127.0f / s;
    for (int j = 0; j < NJ; j++) {
        int c = j * 128 + lane * 4;
        float4 x = *(const float4*)(r + c);
        uint32_t p1, p0; quant4pack(x, rc, p1, p0);
        *(uint32_t*)(d1 + (size_t)row * K + c) = p1;
        *(uint32_t*)(d0 + (size_t)row * K + c) = p0;
    }
    if (lane == 0) sc[row] = s;
}

// -------------------- per-token quantizer (K=2048) ------------------------
__global__ void __launch_bounds__(256) quantF_kernel(
    const float* __restrict__ F, int8_t* __restrict__ F1, int8_t* __restrict__ F0,
    float* __restrict__ sF)
{
    const int t    = blockIdx.x * 8 + (threadIdx.x >> 5);
    const int lane = threadIdx.x & 31;
    const size_t base = (size_t)t * FFDIM;
    float4 v[16];
    float m = 0.f;
    #pragma unroll
    for (int j = 0; j < 16; j++) {
        v[j] = *(const float4*)(F + base + j * 128 + lane * 4);
        m = fmaxf(m, fmaxf(fmaxf(fabsf(v[j].x), fabsf(v[j].y)),
                           fmaxf(fabsf(v[j].z), fabsf(v[j].w))));
    }
    m = warp_max(m);
    const float s = fmaxf(m, 1e-30f);
    const float rc = 127.0f / s;
    #pragma unroll
    for (int j = 0; j < 16; j++) {
        int c = j * 128 + lane * 4;
        uint32_t p1, p0; quant4pack(v[j], rc, p1, p0);
        *(uint32_t*)(F1 + base + c) = p1;
        *(uint32_t*)(F0 + base + c) = p0;
    }
    if (lane == 0) sF[t] = s;
}

// -------------------- per-token quantizer (K=768) -------------------------
__global__ void __launch_bounds__(256) quantO_kernel(
    const float* __restrict__ Osrc, int8_t* __restrict__ X1, int8_t* __restrict__ X0,
    float* __restrict__ sX)
{
    const int t    = blockIdx.x * 8 + (threadIdx.x >> 5);
    const int lane = threadIdx.x & 31;
    const size_t base = (size_t)t * EDIM;
    float4 v[6];
    float m = 0.f;
    #pragma unroll
    for (int j = 0; j < 6; j++) {
        v[j] = *(const float4*)(Osrc + base + j * 128 + lane * 4);
        m = fmaxf(m, fmaxf(fmaxf(fabsf(v[j].x), fabsf(v[j].y)),
                           fmaxf(fabsf(v[j].z), fabsf(v[j].w))));
    }
    m = warp_max(m);
    const float s = fmaxf(m, 1e-30f);
    const float rc = 127.0f / s;
    #pragma unroll
    for (int j = 0; j < 6; j++) {
        int c = j * 128 + lane * 4;
        uint32_t p1, p0; quant4pack(v[j], rc, p1, p0);
        *(uint32_t*)(X1 + base + c) = p1;
        *(uint32_t*)(X0 + base + c) = p0;
    }
    if (lane == 0) sX[t] = s;
}

// -------------------- embed + LN (warp/token) -----------------------------
__global__ void __launch_bounds__(256) embed_ln_kernel(
    const float* __restrict__ tok, const int* __restrict__ pos, const int* __restrict__ typ,
    const float* __restrict__ pe, const float* __restrict__ temb,
    const float* __restrict__ w, const float* __restrict__ bb, float* __restrict__ X,
    int8_t* __restrict__ X1, int8_t* __restrict__ X0, float* __restrict__ sX)
{
    const int t    = blockIdx.x * 8 + (threadIdx.x >> 5);
    const int lane = threadIdx.x & 31;
    const size_t base = (size_t)t * EDIM;
    const float* tr = tok  + base;
    const float* pr = pe   + (size_t)pos[t] * EDIM;
    const float* yr = temb + (size_t)typ[t] * EDIM;
    float4 v[6];
    float sum = 0.f;
    #pragma unroll
    for (int j = 0; j < 6; j++) {
        int c = j * 128 + lane * 4;
        float4 a = *(const float4*)(tr + c);
        float4 p = *(const float4*)(pr + c);
        float4 y = *(const float4*)(yr + c);
        v[j] = make_float4(a.x + p.x + y.x, a.y + p.y + y.y,
                           a.z + p.z + y.z, a.w + p.w + y.w);
        sum += v[j].x + v[j].y + v[j].z + v[j].w;
    }
    const float m = warp_sum(sum) * (1.0f / 768.0f);
    float q = 0.f;
    #pragma unroll
    for (int j = 0; j < 6; j++) {
        float dx = v[j].x - m, dy = v[j].y - m, dz = v[j].z - m, dw = v[j].w - m;
        q += dx * dx + dy * dy + dz * dz + dw * dw;
    }
    const float inv = rsqrtf(warp_sum(q) * (1.0f / 768.0f) + 1e-5f);
    float mx = 0.f;
    #pragma unroll
    for (int j = 0; j < 6; j++) {
        int c = j * 128 + lane * 4;
        float4 wv = *(const float4*)(w + c);
        float4 bv = *(const float4*)(bb + c);
        v[j] = make_float4((v[j].x - m) * inv * wv.x + bv.x,
                           (v[j].y - m) * inv * wv.y + bv.y,
                           (v[j].z - m) * inv * wv.z + bv.z,
                           (v[j].w - m) * inv * wv.w + bv.w);
        *(float4*)(X + base + c) = v[j];
        mx = fmaxf(mx, fmaxf(fmaxf(fabsf(v[j].x), fabsf(v[j].y)),
                             fmaxf(fabsf(v[j].z), fabsf(v[j].w))));
    }
    mx = warp_max(mx);
    const float s = fmaxf(mx, 1e-30f);
    const float rc = 127.0f / s;
    #pragma unroll
    for (int j = 0; j < 6; j++) {
        int c = j * 128 + lane * 4;
        uint32_t p1, p0; quant4pack(v[j], rc, p1, p0);
        *(uint32_t*)(X1 + base + c) = p1;
        *(uint32_t*)(X0 + base + c) = p0;
    }
    if (lane == 0) sX[t] = s;
}

// -------------------- residual + LN (warp/token) --------------------------
template<bool ADD, bool WOUT>
__global__ void __launch_bounds__(256) addln_kernel(
    const float* __restrict__ Xin, const float* __restrict__ Y,
    const float* __restrict__ w, const float* __restrict__ bb, float* __restrict__ Xout,
    int8_t* __restrict__ X1, int8_t* __restrict__ X0, float* __restrict__ sX)
{
    const int t    = blockIdx.x * 8 + (threadIdx.x >> 5);
    const int lane = threadIdx.x & 31;
    const size_t base = (size_t)t * EDIM;
    float4 v[6];
    float sum = 0.f;
    #pragma unroll
    for (int j = 0; j < 6; j++) {
        int c = j * 128 + lane * 4;
        float4 x = *(const float4*)(Xin + base + c);
        if (ADD) {
            float4 y = *(const float4*)(Y + base + c);
            x.x += y.x; x.y += y.y; x.z += y.z; x.w += y.w;
        }
        v[j] = x;
        sum += x.x + x.y + x.z + x.w;
    }
    const float m = warp_sum(sum) * (1.0f / 768.0f);
    float q = 0.f;
    #pragma unroll
    for (int j = 0; j < 6; j++) {
        float dx = v[j].x - m, dy = v[j].y - m, dz = v[j].z - m, dw = v[j].w - m;
        q += dx * dx + dy * dy + dz * dz + dw * dw;
    }
    const float inv = rsqrtf(warp_sum(q) * (1.0f / 768.0f) + 1e-5f);
    float mx = 0.f;
    #pragma unroll
    for (int j = 0; j < 6; j++) {
        int c = j * 128 + lane * 4;
        float4 wv = *(const float4*)(w + c);
        float4 bv = *(const float4*)(bb + c);
        v[j] = make_float4((v[j].x - m) * inv * wv.x + bv.x,
                           (v[j].y - m) * inv * wv.y + bv.y,
                           (v[j].z - m) * inv * wv.z + bv.z,
                           (v[j].w - m) * inv * wv.w + bv.w);
        if (WOUT) *(float4*)(Xout + base + c) = v[j];
        mx = fmaxf(mx, fmaxf(fmaxf(fabsf(v[j].x), fabsf(v[j].y)),
                             fmaxf(fabsf(v[j].z), fabsf(v[j].w))));
    }
    mx = warp_max(mx);
    const float s = fmaxf(mx, 1e-30f);
    const float rc = 127.0f / s;
    #pragma unroll
    for (int j = 0; j < 6; j++) {
        int c = j * 128 + lane * 4;
        uint32_t p1, p0; quant4pack(v[j], rc, p1, p0);
        *(uint32_t*)(X1 + base + c) = p1;
        *(uint32_t*)(X0 + base + c) = p0;
    }
    if (lane == 0) sX[t] = s;
}

// -------------------- int8 two-digit GEMM (4-stage, reordered MMA) --------
#define TG8_STAGE 24576
#define TG8_SMEM  (4 * TG8_STAGE)

__device__ __forceinline__ void tg8_load_stage(
    uint32_t sb, const int8_t* __restrict__ A1b, const int8_t* __restrict__ A0b,
    const int8_t* __restrict__ B1b, const int8_t* __restrict__ B0b,
    int K, int kc, int tid)
{
    #pragma unroll
    for (int t = 0; t < 2; t++) {
        int idx = tid + t * 256;
        int row = idx >> 2;
        int ch  = idx & 3;
        uint32_t soff = (uint32_t)(row * 64 + ((ch ^ ((row >> 1) & 3)) << 4));
        size_t goff = (size_t)row * K + kc + ch * 16;
        CP_ASYNC16(sb +        soff, A1b + goff);
        CP_ASYNC16(sb + 8192 + soff, A0b + goff);
    }
    {
        int row = tid >> 2;
        int ch  = tid & 3;
        uint32_t soff = (uint32_t)(row * 64 + ((ch ^ ((row >> 1) & 3)) << 4));
        size_t goff = (size_t)row * K + kc + ch * 16;
        CP_ASYNC16(sb + 16384 + soff, B1b + goff);
        CP_ASYNC16(sb + 20480 + soff, B0b + goff);
    }
}

template<int ACT, int OSPLIT>
__global__ void __launch_bounds__(256, 2) tgemm_s8_kernel(
    const int8_t* __restrict__ A1, const int8_t* __restrict__ A0,
    const int8_t* __restrict__ B1, const int8_t* __restrict__ B0,
    const float* __restrict__ sA, const float* __restrict__ sB,
    const float* __restrict__ bias, float* __restrict__ C,
    __nv_bfloat16* __restrict__ Chi, __nv_bfloat16* __restrict__ Clo,
    int M, int N, int K)
{
    extern __shared__ __align__(128) unsigned char dsm[];
    const uint32_t sbase = smem_u32(dsm);
    const int tid = threadIdx.x;
    const int w = tid >> 5, l = tid & 31;
    const int wm = w & 3;
    const int wn = w >> 2;
    const int NC = K >> 6;

    const int8_t* A1b = A1 + (size_t)blockIdx.y * 128 * K;
    const int8_t* A0b = A0 + (size_t)blockIdx.y * 128 * K;
    const int8_t* B1b = B1 + (size_t)blockIdx.x * 64 * K;
    const int8_t* B0b = B0 + (size_t)blockIdx.x * 64 * K;

    #pragma unroll
    for (int s = 0; s < 3; s++) {
        tg8_load_stage(sbase + s * TG8_STAGE, A1b, A0b, B1b, B0b, K, s * 64, tid);
        CP_COMMIT();
    }

    int acc1[2][4][4], acc2[2][4][4];
    #pragma unroll
    for (int im = 0; im < 2; im++)
        #pragma unroll
        for (int in = 0; in < 4; in++)
            #pragma unroll
            for (int r = 0; r < 4; r++) { acc1[im][in][r] = 0; acc2[im][in][r] = 0; }

    const int arow = ((l >> 3) & 1) * 8 + (l & 7);
    const int achk = (l >> 4);
    const int axor = (arow >> 1) & 3;
    const int brow = ((l >> 4) << 3) + (l & 7);
    const int bchk = (l >> 3) & 1;
    const int bxor = (brow >> 1) & 3;

    for (int i = 0; i < NC; i++) {
        CP_WAIT2();
        __syncthreads();
        if (i + 3 < NC)
            tg8_load_stage(sbase + ((i + 3) & 3) * TG8_STAGE, A1b, A0b, B1b, B0b, K, (i + 3) * 64, tid);
        CP_COMMIT();

        const uint32_t sb = sbase + (i & 3) * TG8_STAGE;
        #pragma unroll
        for (int ks = 0; ks < 2; ks++) {
            uint32_t b1f[4][2], b0f[4][2];
            #pragma unroll
            for (int p = 0; p < 2; p++) {
                int row = wn * 32 + p * 16 + brow;
                uint32_t bd = sb + 16384 + row * 64 + (((ks * 2 + bchk) ^ bxor) << 4);
                uint32_t t4[4];
                LDSM4(t4, bd);
                b1f[p*2][0] = t4[0]; b1f[p*2][1] = t4[1]; b1f[p*2+1][0] = t4[2]; b1f[p*2+1][1] = t4[3];
                LDSM4(t4, bd + 4096);
                b0f[p*2][0] = t4[0]; b0f[p*2][1] = t4[1]; b0f[p*2+1][0] = t4[2]; b0f[p*2+1][1] = t4[3];
            }
            uint32_t a1f[2][4], a0f[2][4];
            #pragma unroll
            for (int im = 0; im < 2; im++) {
                int row = wm * 32 + im * 16 + arow;
                uint32_t ad = sb + row * 64 + (((ks * 2 + achk) ^ axor) << 4);
                LDSM4(a1f[im], ad);
                LDSM4(a0f[im], ad + 8192);
            }
            // pass 1: acc1 += a1*b1 (8 independent MMAs)
            #pragma unroll
            for (int im = 0; im < 2; im++)
                #pragma unroll
                for (int in = 0; in < 4; in++)
                    MMA_S8(acc1[im][in], a1f[im], b1f[in][0], b1f[in][1]);
            // pass 2: acc2 += a1*b0 (8 independent MMAs)
            #pragma unroll
            for (int im = 0; im < 2; im++)
                #pragma unroll
                for (int in = 0; in < 4; in++)
                    MMA_S8(acc2[im][in], a1f[im], b0f[in][0], b0f[in][1]);
            // pass 3: acc2 += a0*b1 (each dep is 8 MMAs back)
            #pragma unroll
            for (int im = 0; im < 2; im++)
                #pragma unroll
                for (int in = 0; in < 4; in++)
                    MMA_S8(acc2[im][in], a0f[im], b1f[in][0], b1f[in][1]);
        }
    }

    const float CINV = 1.0f / 16129.0f;
    #pragma unroll
    for (int im = 0; im < 2; im++) {
        const int r0 = blockIdx.y * 128 + wm * 32 + im * 16 + (l >> 2);
        const float sa0 = sA[r0] * CINV;
        const float sa8 = sA[r0 + 8] * CINV;
        #pragma unroll
        for (int in = 0; in < 4; in++) {
            const int c0 = blockIdx.x * 64 + wn * 32 + in * 8 + (l & 3) * 2;
            const float sb0 = sB[c0], sb1 = sB[c0 + 1];
            float f00 = (float)acc1[im][in][0] + (float)acc2[im][in][0] * (1.0f / 254.0f);
            float f01 = (float)acc1[im][in][1] + (float)acc2[im][in][1] * (1.0f / 254.0f);
            float f10 = (float)acc1[im][in][2] + (float)acc2[im][in][2] * (1.0f / 254.0f);
            float f11 = (float)acc1[im][in][3] + (float)acc2[im][in][3] * (1.0f / 254.0f);
            float v00 = sa0 * sb0 * f00 + bias[c0];
            float v01 = sa0 * sb1 * f01 + bias[c0 + 1];
            float v10 = sa8 * sb0 * f10 + bias[c0];
            float v11 = sa8 * sb1 * f11 + bias[c0 + 1];
            if (ACT == 1) {
                v00 = fmaxf(v00, 0.f); v01 = fmaxf(v01, 0.f);
                v10 = fmaxf(v10, 0.f); v11 = fmaxf(v11, 0.f);
            }
            if (ACT == 2) {
                v00 = tanhf(v00); v01 = tanhf(v01);
                v10 = tanhf(v10); v11 = tanhf(v11);
            }
            if (OSPLIT == 0) {
                *(float2*)(C + (size_t)r0 * N + c0)       = make_float2(v00, v01);
                *(float2*)(C + (size_t)(r0 + 8) * N + c0) = make_float2(v10, v11);
            } else {
                union { __nv_bfloat16 b[2]; uint32_t u; } h0, l0, h1, l1;
                split_bf16(v00, h0.b[0], l0.b[0]); split_bf16(v01, h0.b[1], l0.b[1]);
                split_bf16(v10, h1.b[0], l1.b[0]); split_bf16(v11, h1.b[1], l1.b[1]);
                *(uint32_t*)(Chi + (size_t)r0 * N + c0)       = h0.u;
                *(uint32_t*)(Clo + (size_t)r0 * N + c0)       = l0.u;
                *(uint32_t*)(Chi + (size_t)(r0 + 8) * N + c0) = h1.u;
                *(uint32_t*)(Clo + (size_t)(r0 + 8) * N + c0) = l1.u;
            }
        }
    }
}

// -------------------- tensor-core attention (reordered MMA) ---------------
#define ATTN_SMEM3 (112 * 1024)

__global__ void __launch_bounds__(256, 2) attn_mma_kernel(
    const __nv_bfloat16* __restrict__ QKVh, const __nv_bfloat16* __restrict__ QKVl,
    float* __restrict__ AO)
{
    extern __shared__ __align__(128) unsigned char asm_[];
    const uint32_t S0  = smem_u32(asm_);
    const uint32_t S1  = S0 + 32768;
    const uint32_t QH  = S0 + 65536;
    const uint32_t KVH = S0 + 81920;

    const int tid = threadIdx.x;
    const int w = tid >> 5, lane = tid & 31;
    const int qt = blockIdx.x;
    const int bh = blockIdx.y;
    const int b = bh / NH, h = bh % NH;
    const size_t tok0 = (size_t)b * SEQ;

    const int a_r = lane & 15;
    const int a_c = lane >> 4;
    const int b_r = ((lane >> 4) << 3) + (lane & 7);
    const int b_c = (lane >> 3) & 1;
    const int warp_m = w & 1, warp_n = w >> 1;

    #pragma unroll
    for (int i = 0; i < 2; i++) {
        int idx = tid + i * 256; int r = idx >> 3, ch = idx & 7;
        uint32_t so = r * 128 + ((ch ^ (r & 7)) << 4);
        size_t go = (tok0 + qt * 64 + r) * E3 + h * HDIM + ch * 8;
        CP_ASYNC16(QH + so, QKVh + go);
        CP_ASYNC16(QH + 8192 + so, QKVl + go);
    }
    #pragma unroll
    for (int i = 0; i < 4; i++) {
        int idx = tid + i * 256; int r = idx >> 3, ch = idx & 7;
        uint32_t so = r * 128 + ((ch ^ (r & 7)) << 4);
        size_t go = (tok0 + r) * E3 + EDIM + h * HDIM + ch * 8;
        CP_ASYNC16(KVH + so, QKVh + go);
        CP_ASYNC16(KVH + 16384 + so, QKVl + go);
    }
    CP_COMMIT();
    CP_WAIT0();
    __syncthreads();

    #pragma unroll 1
    for (int half = 0; half < 2; half++) {
        if (half == 1) {
            __syncthreads();
            #pragma unroll
            for (int i = 0; i < 4; i++) {
                int idx = tid + i * 256; int r = idx >> 3, ch = idx & 7;
                uint32_t so = r * 128 + ((ch ^ (r & 7)) << 4);
                size_t go = (tok0 + 128 + r) * E3 + EDIM + h * HDIM + ch * 8;
                CP_ASYNC16(KVH + so, QKVh + go);
                CP_ASYNC16(KVH + 16384 + so, QKVl + go);
            }
            CP_COMMIT();
            CP_WAIT0();
            __syncthreads();
        }

        float acc[2][4][4];
        #pragma unroll
        for (int im = 0; im < 2; im++)
            #pragma unroll
            for (int in = 0; in < 4; in++)
                #pragma unroll
                for (int r = 0; r < 4; r++) acc[im][in][r] = 0.f;

        #pragma unroll
        for (int ks = 0; ks < 4; ks++) {
            uint32_t aH[2][4], aL[2][4], bH[4][2], bL[4][2];
            #pragma unroll
            for (int im = 0; im < 2; im++) {
                int r = warp_m * 32 + im * 16 + a_r;
                int cc = ks * 2 + a_c;
                uint32_t ad = QH + r * 128 + ((cc ^ (r & 7)) << 4);
                LDSM4(aH[im], ad);
                LDSM4(aL[im], ad + 8192);
            }
            #pragma unroll
            for (int p = 0; p < 2; p++) {
                int r = warp_n * 32 + p * 16 + b_r;
                int cc = ks * 2 + b_c;
                uint32_t bd = KVH + r * 128 + ((cc ^ (r & 7)) << 4);
                uint32_t t4[4];
                LDSM4(t4, bd);
                bH[p*2][0] = t4[0]; bH[p*2][1] = t4[1]; bH[p*2+1][0] = t4[2]; bH[p*2+1][1] = t4[3];
                LDSM4(t4, bd + 16384);
                bL[p*2][0] = t4[0]; bL[p*2][1] = t4[1]; bL[p*2+1][0] = t4[2]; bL[p*2+1][1] = t4[3];
            }
            // pass 1: aH*bH (8 independent)
            #pragma unroll
            for (int im = 0; im < 2; im++)
                #pragma unroll
                for (int in = 0; in < 4; in++)
                    MMA_BF16(acc[im][in], aH[im], bH[in][0], bH[in][1]);
            // pass 2: aH*bL (dep 8 back)
            #pragma unroll
            for (int im = 0; im < 2; im++)
                #pragma unroll
                for (int in = 0; in < 4; in++)
                    MMA_BF16(acc[im][in], aH[im], bL[in][0], bL[in][1]);
            // pass 3: aL*bH (dep 8 back)
            #pragma unroll
            for (int im = 0; im < 2; im++)
                #pragma unroll
                for (int in = 0; in < 4; in++)
                    MMA_BF16(acc[im][in], aL[im], bH[in][0], bH[in][1]);
        }

        const uint32_t Sb = (half == 0) ? S0 : S1;
        #pragma unroll
        for (int im = 0; im < 2; im++) {
            int r0 = warp_m * 32 + im * 16 + (lane >> 2);
            int r1 = r0 + 8;
            #pragma unroll
            for (int in = 0; in < 4; in++) {
                int c = warp_n * 32 + in * 8 + (lane & 3) * 2;
                uint32_t a0 = Sb + r0 * 512 + (((c >> 2) ^ (r0 & 7)) << 4) + (c & 3) * 4;
                uint32_t a1 = Sb + r1 * 512 + (((c >> 2) ^ (r1 & 7)) << 4) + (c & 3) * 4;
                asm volatile("st.shared.v2.f32 [%0], {%1,%2};"
                    :: "r"(a0), "f"(acc[im][in][0] * 0.125f), "f"(acc[im][in][1] * 0.125f) : "memory");
                asm volatile("st.shared.v2.f32 [%0], {%1,%2};"
                    :: "r"(a1), "f"(acc[im][in][2] * 0.125f), "f"(acc[im][in][3] * 0.125f) : "memory");
            }
        }
    }
    __syncthreads();

    #pragma unroll
    for (int i = 0; i < 4; i++) {
        int idx = tid + i * 256; int r = idx >> 3, ch = idx & 7;
        uint32_t so = r * 128 + ((ch ^ (r & 7)) << 4);
        size_t go = (tok0 + r) * E3 + 2 * EDIM + h * HDIM + ch * 8;
        CP_ASYNC16(KVH + so, QKVh + go);
        CP_ASYNC16(KVH + 16384 + so, QKVl + go);
    }
    CP_COMMIT();

    for (int rr = 0; rr < 8; rr++) {
        const int r = w * 8 + rr;
        const uint32_t Sb = (lane < 16) ? S0 : S1;
        const int ch2 = 2 * (lane & 15);
        const uint32_t base = Sb + r * 512;
        float v[8];
        asm volatile("ld.shared.v4.f32 {%0,%1,%2,%3}, [%4];"
            : "=f"(v[0]), "=f"(v[1]), "=f"(v[2]), "=f"(v[3])
            : "r"(base + ((ch2 ^ (r & 7)) << 4)));
        asm volatile("ld.shared.v4.f32 {%0,%1,%2,%3}, [%4];"
            : "=f"(v[4]), "=f"(v[5]), "=f"(v[6]), "=f"(v[7])
            : "r"(base + (((ch2 + 1) ^ (r & 7)) << 4)));
        float mx = v[0];
        #pragma unroll
        for (int j = 1; j < 8; j++) mx = fmaxf(mx, v[j]);
        #pragma unroll
        for (int o = 16; o > 0; o >>= 1) mx = fmaxf(mx, __shfl_xor_sync(0xffffffffu, mx, o));
        float s = 0.f;
        #pragma unroll
        for (int j = 0; j < 8; j++) { v[j] = expf(v[j] - mx); s += v[j]; }
        #pragma unroll
        for (int o = 16; o > 0; o >>= 1) s += __shfl_xor_sync(0xffffffffu, s, o);
        const float inv = 1.0f / s;
        union { __nv_bfloat16 b[8]; uint4 u; } ph, pl;
        #pragma unroll
        for (int j = 0; j < 8; j++) {
            float p = v[j] * inv;
            split_bf16(p, ph.b[j], pl.b[j]);
        }
        __syncwarp();
        const uint32_t pc = r * 512 + ((lane ^ (r & 7)) << 4);
        asm volatile("st.shared.v4.b32 [%0], {%1,%2,%3,%4};"
            :: "r"(S0 + pc), "r"(ph.u.x), "r"(ph.u.y), "r"(ph.u.z), "r"(ph.u.w) : "memory");
        asm volatile("st.shared.v4.b32 [%0], {%1,%2,%3,%4};"
            :: "r"(S1 + pc), "r"(pl.u.x), "r"(pl.u.y), "r"(pl.u.z), "r"(pl.u.w) : "memory");
    }
    CP_WAIT0();
    __syncthreads();

    const int wm2 = w & 1, wn2 = w >> 1;
    float acc2[2][2][4];
    #pragma unroll
    for (int im = 0; im < 2; im++)
        #pragma unroll
        for (int in = 0; in < 2; in++)
            #pragma unroll
            for (int r = 0; r < 4; r++) acc2[im][in][r] = 0.f;

    #pragma unroll 1
    for (int chunk = 0; chunk < 2; chunk++) {
        if (chunk == 1) {
            __syncthreads();
            #pragma unroll
            for (int i = 0; i < 4; i++) {
                int idx = tid + i * 256; int r = idx >> 3, ch = idx & 7;
                uint32_t so = r * 128 + ((ch ^ (r & 7)) << 4);
                size_t go = (tok0 + 128 + r) * E3 + 2 * EDIM + h * HDIM + ch * 8;
                CP_ASYNC16(KVH + so, QKVh + go);
                CP_ASYNC16(KVH + 16384 + so, QKVl + go);
            }
            CP_COMMIT();
            CP_WAIT0();
            __syncthreads();
        }
        #pragma unroll
        for (int ks = 0; ks < 8; ks++) {
            uint32_t aH[2][4], aL[2][4], bH[2][2], bL[2][2];
            #pragma unroll
            for (int im = 0; im < 2; im++) {
                int r = wm2 * 32 + im * 16 + a_r;
                int cc = (chunk * 8 + ks) * 2 + a_c;
                uint32_t ad = r * 512 + ((cc ^ (r & 7)) << 4);
                LDSM4(aH[im], S0 + ad);
                LDSM4(aL[im], S1 + ad);
            }
            {
                int n0 = wn2 * 16;
                int kr = ks * 16 + ((lane >> 3) & 1) * 8 + (lane & 7);
                int cn = (n0 >> 3) + (lane >> 4);
                uint32_t bd = KVH + kr * 128 + ((cn ^ (kr & 7)) << 4);
                uint32_t t4[4];
                LDSM4T(t4, bd);
                bH[0][0] = t4[0]; bH[0][1] = t4[1]; bH[1][0] = t4[2]; bH[1][1] = t4[3];
                LDSM4T(t4, bd + 16384);
                bL[0][0] = t4[0]; bL[0][1] = t4[1]; bL[1][0] = t4[2]; bL[1][1] = t4[3];
            }
            // pass 1: aH*bH (4 independent)
            #pragma unroll
            for (int im = 0; im < 2; im++)
                #pragma unroll
                for (int in = 0; in < 2; in++)
                    MMA_BF16(acc2[im][in], aH[im], bH[in][0], bH[in][1]);
            // pass 2: aH*bL (dep 4 back)
            #pragma unroll
            for (int im = 0; im < 2; im++)
                #pragma unroll
                for (int in = 0; in < 2; in++)
                    MMA_BF16(acc2[im][in], aH[im], bL[in][0], bL[in][1]);
            // pass 3: aL*bH (dep 4 back)
            #pragma unroll
            for (int im = 0; im < 2; im++)
                #pragma unroll
                for (int in = 0; in < 2; in++)
                    MMA_BF16(acc2[im][in], aL[im], bH[in][0], bH[in][1]);
        }
    }

    #pragma unroll
    for (int im = 0; im < 2; im++) {
        int rloc = wm2 * 32 + im * 16 + (lane >> 2);
        size_t t0 = (tok0 + qt * 64 + rloc) * EDIM;
        size_t t1 = (tok0 + qt * 64 + rloc + 8) * EDIM;
        #pragma unroll
        for (int in = 0; in < 2; in++) {
            int c = h * HDIM + wn2 * 16 + in * 8 + (lane & 3) * 2;
            *(float2*)(AO + t0 + c) = make_float2(acc2[im][in][0], acc2[im][in][1]);
            *(float2*)(AO + t1 + c) = make_float2(acc2[im][in][2], acc2[im][in][3]);
        }
    }
}

// -------------------- cosine --------------------
__global__ void __launch_bounds__(256) cos_kernel(
    const float* __restrict__ tok, const float* __restrict__ out, float* __restrict__ cosb)
{
    const int t = blockIdx.x * 8 + (threadIdx.x >> 5);
    const int l = threadIdx.x & 31;
    const float* a = tok + (size_t)t * EDIM;
    const float* b = out + (size_t)t * EDIM;
    float dot = 0.f, na = 0.f, nb = 0.f;
    #pragma unroll
    for (int j = 0; j < 6; j++) {
        int c = j * 128 + l * 4;
        float4 x = *(const float4*)(a + c);
        float4 y = *(const float4*)(b + c);
        dot += x.x * y.x + x.y * y.y + x.z * y.z + x.w * y.w;
        na  += x.x * x.x + x.y * x.y + x.z * x.z + x.w * x.w;
        nb  += y.x * y.x + y.y * y.y + y.z * y.z + y.w * y.w;
    }
    dot = warp_sum(dot);
    na  = warp_sum(na);
    nb  = warp_sum(nb);
    if (l == 0)
        cosb[t] = dot / fmaxf(sqrtf(na) * sqrtf(nb), 1e-8f);
}

// -------------------- masked softmax + gumbel top-k --------------------
__global__ void __launch_bounds__(256) topk_kernel(
    const float* __restrict__ cosb, const float* __restrict__ gh, const float* __restrict__ gt,
    const int* __restrict__ typ, float* __restrict__ out)
{
    __shared__ float red[8];
    __shared__ float glh[256], glt[256];
    const int b = blockIdx.x, s = threadIdx.x;
    const int idx = b * SEQ + s;
    const int t = typ[idx];
    const float c = cosb[idx];
    const bool vh = (t == 1), vt = (t == 2);
    float eh = vh ? expf(c) : 0.f;
    float et = vt ? expf(c) : 0.f;
    float Zh = block_sum256(eh, red);
    float Zt = block_sum256(et, red);
    glh[s] = vh ? (logf(eh / Zh) + gh[idx]) : -1e30f;
    glt[s] = vt ? (logf(1.0f - et / Zt) + gt[idx]) : -1e30f;
    __syncthreads();
    int ch = 0, ct = 0;
    const float mh = glh[s], mt = glt[s];
    for (int j = 0; j < 256; j++) {
        float a = glh[j], d = glt[j];
        ch += (a > mh) || (a == mh && j < s);
        ct += (d > mt) || (d == mt && j < s);
    }
    float r = 0.f;
    if (vh && ch < 64) r += 1.0f;
    if (vt && ct < 63) r += 1.0f;
    out[idx] = r;
}

// -------------------- host orchestration --------------------
extern "C" void kernel_launch(void* const* d_in, const int* in_sizes, int n_in,
                              void* d_out, int out_size)
{
    const float* tok  = (const float*)d_in[0];
    const int*   pos  = (const int*)  d_in[2];
    const int*   typ  = (const int*)  d_in[3];
    const float* gh   = (const float*)d_in[4];
    const float* gt   = (const float*)d_in[5];
    const float* pe   = (const float*)d_in[6];
    const float* temb = (const float*)d_in[7];
    const float* lnw  = (const float*)d_in[8];
    const float* lnb  = (const float*)d_in[9];
    const float* dw   = (const float*)d_in[10];
    const float* db   = (const float*)d_in[11];
    const float* qkvw = (const float*)d_in[12];
    const float* qkvb = (const float*)d_in[13];
    const float* ow   = (const float*)d_in[14];
    const float* obv  = (const float*)d_in[15];
    const float* ln1w = (const float*)d_in[16];
    const float* ln1b = (const float*)d_in[17];
    const float* l1w  = (const float*)d_in[18];
    const float* l1b  = (const float*)d_in[19];
    const float* l2w  = (const float*)d_in[20];
    const float* l2b  = (const float*)d_in[21];
    const float* ln2w = (const float*)d_in[22];
    const float* ln2b = (const float*)d_in[23];

    float *X, *Y, *O, *AO, *C, *Ff;
    __nv_bfloat16 *QKVh, *QKVl;
    int8_t *X1, *X0, *F1, *F0, *Wq1, *Wq0, *Wo1, *Wo0, *W1d1, *W1d0, *W2d1, *W2d0, *Wdd1, *Wdd0;
    float *sX, *sF, *sWq, *sWo, *sW1, *sW2, *sWd;
    cudaGetSymbolAddress((void**)&X,    g_X);
    cudaGetSymbolAddress((void**)&Y,    g_Yb);
    cudaGetSymbolAddress((void**)&O,    g_O);
    cudaGetSymbolAddress((void**)&AO,   g_AO);
    cudaGetSymbolAddress((void**)&C,    g_C);
    cudaGetSymbolAddress((void**)&Ff,   g_Ff);
    cudaGetSymbolAddress((void**)&QKVh, g_QKVh);
    cudaGetSymbolAddress((void**)&QKVl, g_QKVl);
    cudaGetSymbolAddress((void**)&X1, g_X1); cudaGetSymbolAddress((void**)&X0, g_X0);
    cudaGetSymbolAddress((void**)&F1, g_F1); cudaGetSymbolAddress((void**)&F0, g_F0);
    cudaGetSymbolAddress((void**)&Wq1, g_Wq1); cudaGetSymbolAddress((void**)&Wq0, g_Wq0);
    cudaGetSymbolAddress((void**)&Wo1, g_Wo1); cudaGetSymbolAddress((void**)&Wo0, g_Wo0);
    cudaGetSymbolAddress((void**)&W1d1, g_W1d1); cudaGetSymbolAddress((void**)&W1d0, g_W1d0);
    cudaGetSymbolAddress((void**)&W2d1, g_W2d1); cudaGetSymbolAddress((void**)&W2d0, g_W2d0);
    cudaGetSymbolAddress((void**)&Wdd1, g_Wdd1); cudaGetSymbolAddress((void**)&Wdd0, g_Wdd0);
    cudaGetSymbolAddress((void**)&sX, g_sX); cudaGetSymbolAddress((void**)&sF, g_sF);
    cudaGetSymbolAddress((void**)&sWq, g_sWq); cudaGetSymbolAddress((void**)&sWo, g_sWo);
    cudaGetSymbolAddress((void**)&sW1, g_sW1); cudaGetSymbolAddress((void**)&sW2, g_sW2);
    cudaGetSymbolAddress((void**)&sWd, g_sWd);

    cudaFuncSetAttribute(attn_mma_kernel, cudaFuncAttributeMaxDynamicSharedMemorySize, ATTN_SMEM3);
    cudaFuncSetAttribute(tgemm_s8_kernel<0,0>, cudaFuncAttributeMaxDynamicSharedMemorySize, TG8_SMEM);
    cudaFuncSetAttribute(tgemm_s8_kernel<1,0>, cudaFuncAttributeMaxDynamicSharedMemorySize, TG8_SMEM);
    cudaFuncSetAttribute(tgemm_s8_kernel<0,1>, cudaFuncAttributeMaxDynamicSharedMemorySize, TG8_SMEM);
    cudaFuncSetAttribute(tgemm_s8_kernel<2,0>, cudaFuncAttributeMaxDynamicSharedMemorySize, TG8_SMEM);

    embed_ln_kernel<<<NTOK / 8, 256>>>(tok, pos, typ, pe, temb, lnw, lnb, X, X1, X0, sX);
    quant_rows_kernel<<<(2 * E3) / 8, 256>>>(qkvw, Wq1, Wq0, sWq, EDIM);
    quant_rows_kernel<<<(2 * EDIM) / 8, 256>>>(ow, Wo1, Wo0, sWo, EDIM);
    quant_rows_kernel<<<(2 * FFDIM) / 8, 256>>>(l1w, W1d1, W1d0, sW1, EDIM);
    quant_rows_kernel<<<(2 * EDIM) / 8, 256>>>(l2w, W2d1, W2d0, sW2, FFDIM);
    quant_rows_kernel<<<EDIM / 8, 256>>>(dw, Wdd1, Wdd0, sWd, EDIM);

    for (int l = 0; l < 2; l++) {
        tgemm_s8_kernel<0,1><<<dim3(E3 / 64, NTOK / 128), 256, TG8_SMEM>>>(
            X1, X0, Wq1 + (size_t)l * E3 * EDIM, Wq0 + (size_t)l * E3 * EDIM,
            sX, sWq + (size_t)l * E3, qkvb + (size_t)l * E3,
            nullptr, QKVh, QKVl, NTOK, E3, EDIM);
        attn_mma_kernel<<<dim3(4, NB * NH), 256, ATTN_SMEM3>>>(QKVh, QKVl, AO);
        quantO_kernel<<<NTOK / 8, 256>>>(AO, X1, X0, sX);
        tgemm_s8_kernel<0,0><<<dim3(EDIM / 64, NTOK / 128), 256, TG8_SMEM>>>(
            X1, X0, Wo1 + (size_t)l * EDIM * EDIM, Wo0 + (size_t)l * EDIM * EDIM,
            sX, sWo + (size_t)l * EDIM, obv + (size_t)l * EDIM,
            Y, nullptr, nullptr, NTOK, EDIM, EDIM);
        addln_kernel<true, true><<<NTOK / 8, 256>>>(X, Y, ln1w + (size_t)l * EDIM,
            ln1b + (size_t)l * EDIM, X, X1, X0, sX);
        tgemm_s8_kernel<1,0><<<dim3(FFDIM / 64, NTOK / 128), 256, TG8_SMEM>>>(
            X1, X0, W1d1 + (size_t)l * FFDIM * EDIM, W1d0 + (size_t)l * FFDIM * EDIM,
            sX, sW1 + (size_t)l * FFDIM, l1b + (size_t)l * FFDIM,
            Ff, nullptr, nullptr, NTOK, FFDIM, EDIM);
        quantF_kernel<<<NTOK / 8, 256>>>(Ff, F1, F0, sF);
        tgemm_s8_kernel<0,0><<<dim3(EDIM / 64, NTOK / 128), 256, TG8_SMEM>>>(
            F1, F0, W2d1 + (size_t)l * EDIM * FFDIM, W2d0 + (size_t)l * EDIM * FFDIM,
            sF, sW2 + (size_t)l * EDIM, l2b + (size_t)l * EDIM,
            Y, nullptr, nullptr, NTOK, EDIM, FFDIM);
        addln_kernel<true, true><<<NTOK / 8, 256>>>(X, Y, ln2w + (size_t)l * EDIM,
            ln2b + (size_t)l * EDIM, X, X1, X0, sX);
    }

    addln_kernel<false, false><<<NTOK / 8, 256>>>(X, nullptr, lnw, lnb, nullptr, X1, X0, sX);
    tgemm_s8_kernel<2,0><<<dim3(EDIM / 64, NTOK / 128), 256, TG8_SMEM>>>(
        X1, X0, Wdd1, Wdd0, sX, sWd, db, O, nullptr, nullptr, NTOK, EDIM, EDIM);
    cos_kernel<<<NTOK / 8, 256>>>(tok, O, C);
    topk_kernel<<<NB, 256>>>(C, gh, gt, typ, (float*)d_out);
}